// round 15
// baseline (speedup 1.0000x reference)
#include <cuda_runtime.h>
#include <cuda_fp16.h>
#include <stdint.h>
#include <string.h>
#include <math.h>

typedef __half fp16;

constexpr int DM = 192;
constexpr int MAXB = 65536;
constexpr long NT = 2L * MAXB;

// fp32 scratch
__device__ float g_seq[NT * DM];
__device__ float g_x[NT * DM];

// fp16 activation scratch
__device__ fp16 g_pa[(long)MAXB * DM], g_ta[(long)MAXB * DM];
__device__ fp16 g_seqh[NT * DM];
__device__ fp16 g_qkvh[NT * 3 * DM];
__device__ fp16 g_ctxh[NT * DM];
__device__ fp16 g_xh[NT * DM];
__device__ fp16 g_hh[NT * 2 * DM];
__device__ fp16 g_zh[(long)MAXB * DM];

// fp16 weight scratch
constexpr int OW_P = 0, OW_T = 36864, OW_IN = 73728, OW_OUT = 184320;
constexpr int OW_F1 = 221184, OW_F2 = 294912, OW_CLS = 368640, OW_FP = 405504;
constexpr int OW_TOT = 430080;
__device__ fp16 g_whi[OW_TOT];

// ---------------- helpers ----------------
__device__ __forceinline__ uint32_t smem_u32(const void* p) {
    uint32_t a;
    asm("{ .reg .u64 t; cvta.to.shared.u64 t, %1; cvt.u32.u64 %0, t; }" : "=r"(a) : "l"(p));
    return a;
}
__device__ __forceinline__ void cp16(uint32_t dst, const void* src) {
    asm volatile("cp.async.cg.shared.global [%0], [%1], 16;" :: "r"(dst), "l"(src));
}
__device__ __forceinline__ void cp_commit() { asm volatile("cp.async.commit_group;"); }
__device__ __forceinline__ void cp_wait1() { asm volatile("cp.async.wait_group 1;"); }
__device__ __forceinline__ void ldsm_x4(uint32_t* r, uint32_t addr) {
    asm volatile("ldmatrix.sync.aligned.m8n8.x4.shared.b16 {%0,%1,%2,%3}, [%4];"
        : "=r"(r[0]), "=r"(r[1]), "=r"(r[2]), "=r"(r[3]) : "r"(addr));
}
__device__ __forceinline__ void mma16816(float* c, const uint32_t* a, const uint32_t* b) {
    asm volatile(
        "mma.sync.aligned.m16n8k16.row.col.f32.f16.f16.f32 "
        "{%0,%1,%2,%3}, {%4,%5,%6,%7}, {%8,%9}, {%0,%1,%2,%3};"
        : "+f"(c[0]), "+f"(c[1]), "+f"(c[2]), "+f"(c[3])
        : "r"(a[0]), "r"(a[1]), "r"(a[2]), "r"(a[3]), "r"(b[0]), "r"(b[1]));
}
__device__ __forceinline__ uint32_t pack_h2(float x, float y) {
    __half2 h = __floats2half2_rn(x, y);
    uint32_t u; memcpy(&u, &h, 4); return u;
}

__global__ void cvt_k(const float* __restrict__ s, fp16* __restrict__ o, long n)
{
    long i = 4L * (blockIdx.x * (long)blockDim.x + threadIdx.x);
    if (i >= n) return;
    float4 v = *(const float4*)(s + i);
    *(uint32_t*)(o + i) = pack_h2(v.x, v.y);
    *(uint32_t*)(o + i + 2) = pack_h2(v.z, v.w);
}

__global__ void cvt_weights(const float* __restrict__ wp, const float* __restrict__ wt,
                            const float* __restrict__ inw, const float* __restrict__ ow,
                            const float* __restrict__ f1, const float* __restrict__ f2,
                            const float* __restrict__ cls, const float* __restrict__ fpw,
                            fp16* __restrict__ dst)
{
    long i = 4L * (blockIdx.x * (long)blockDim.x + threadIdx.x);
    if (i >= OW_TOT) return;
    const float* src;
    long off;
    if      (i < OW_T)   { src = wp;  off = i - OW_P; }
    else if (i < OW_IN)  { src = wt;  off = i - OW_T; }
    else if (i < OW_OUT) { src = inw; off = i - OW_IN; }
    else if (i < OW_F1)  { src = ow;  off = i - OW_OUT; }
    else if (i < OW_F2)  { src = f1;  off = i - OW_F1; }
    else if (i < OW_CLS) { src = f2;  off = i - OW_F2; }
    else if (i < OW_FP)  { src = cls; off = i - OW_CLS; }
    else                 { src = fpw; off = i - OW_FP; }
    float4 v = *(const float4*)(src + off);
    *(uint32_t*)(dst + i) = pack_h2(v.x, v.y);
    *(uint32_t*)(dst + i + 2) = pack_h2(v.z, v.w);
}

// ---------------------------------------------------------------------------
// fp16 HMMA GEMM, 3-stage cp.async, ldmatrix. Low-register inner loop:
// per jp group, load 4 B-frag regs and immediately run 4 MMAs.
// ---------------------------------------------------------------------------
template<int BN> struct StgSz { static constexpr int v = 2560 + BN * 20; };
constexpr int GEMM_SMEM96 = 3 * StgSz<96>::v * 4;
constexpr int LN_SMEM  = 2 * StgSz<192>::v * 4;
constexpr int FP_SMEM  = 2 * StgSz<128>::v * 4;

template<int BN, bool RELU, bool WF32, bool WH16>
__global__ void __launch_bounds__(256, 3)
tc_gemm(const fp16* __restrict__ Ag, int lda,
        const fp16* __restrict__ Whg,
        const float* __restrict__ bias,
        float* __restrict__ C, int ldc, int coff,
        fp16* __restrict__ S, int lds_, int scoff,
        int K)
{
    constexpr int NJ = BN / 16;
    constexpr int NJP = BN / 32;
    constexpr int STG = StgSz<BN>::v;

    extern __shared__ __align__(16) uint32_t sm32[];
    const uint32_t sbase = smem_u32(sm32);
    const int tid = threadIdx.x;
    const int wid = tid >> 5, lane = tid & 31;
    const int wr = wid >> 1, wc = wid & 1;
    const int m0 = blockIdx.y * 128, n0 = blockIdx.x * BN;

    float acc[2][NJ][4];
#pragma unroll
    for (int i = 0; i < 2; i++)
#pragma unroll
        for (int j = 0; j < NJ; j++)
#pragma unroll
            for (int q = 0; q < 4; q++) acc[i][j][q] = 0.f;

    const int lr = tid >> 2, seg = tid & 3;
    const int t7 = lane & 7, mi = lane >> 3;
    const int aRow0 = wr * 32 + t7 + (mi & 1) * 8;
    const int aCol  = (mi >> 1) * 4;
    const int bRow0 = wc * (BN / 2) + t7 + (mi >> 1) * 8;
    const int bCol  = (mi & 1) * 4;
    const int nc = K >> 5;

    auto issue = [&](int c) {
        const int k0 = c << 5;
        const uint32_t sb = sbase + (c % 3) * (STG * 4);
#pragma unroll
        for (int it = 0; it < 2; it++) {
            const int r = lr + it * 64;
            cp16(sb + (r * 20 + seg * 4) * 4, Ag + (size_t)(m0 + r) * lda + k0 + seg * 8);
        }
#pragma unroll
        for (int i = tid; i < BN * 4; i += 256) {
            const int r = i >> 2, sg = i & 3;
            cp16(sb + (2560 + r * 20 + sg * 4) * 4, Whg + (size_t)(n0 + r) * K + k0 + sg * 8);
        }
    };

    issue(0); cp_commit();
    if (nc > 1) { issue(1); cp_commit(); } else cp_commit();

    for (int c = 0; c < nc; c++) {
        cp_wait1();
        __syncthreads();
        if (c + 2 < nc) issue(c + 2);
        cp_commit();

        const uint32_t sb = sbase + (c % 3) * (STG * 4);
#pragma unroll
        for (int s = 0; s < 2; s++) {
            uint32_t ah[2][4];
#pragma unroll
            for (int i = 0; i < 2; i++) {
                const uint32_t ai = (uint32_t)((aRow0 + i * 16) * 20 + s * 8 + aCol) * 4;
                ldsm_x4(ah[i], sb + ai);
            }
#pragma unroll
            for (int jp = 0; jp < NJP; jp++) {
                const uint32_t bi = (uint32_t)((bRow0 + jp * 16) * 20 + s * 8 + bCol) * 4;
                uint32_t tb[4];
                ldsm_x4(tb, sb + 2560 * 4 + bi);
                mma16816(acc[0][2 * jp],     ah[0], tb);
                mma16816(acc[0][2 * jp + 1], ah[0], tb + 2);
                mma16816(acc[1][2 * jp],     ah[1], tb);
                mma16816(acc[1][2 * jp + 1], ah[1], tb + 2);
            }
        }
    }

    const int lg = lane >> 2, lq = lane & 3;
#pragma unroll
    for (int i = 0; i < 2; i++) {
        const int row = m0 + wr * 32 + i * 16 + lg;
#pragma unroll
        for (int j = 0; j < NJ; j++) {
            const int col = n0 + wc * (BN / 2) + j * 8 + 2 * lq;
            const float bx = bias[col], by = bias[col + 1];
            float2 v0, v1;
            v0.x = acc[i][j][0] + bx; v0.y = acc[i][j][1] + by;
            v1.x = acc[i][j][2] + bx; v1.y = acc[i][j][3] + by;
            if (RELU) {
                v0.x = fmaxf(v0.x, 0.f); v0.y = fmaxf(v0.y, 0.f);
                v1.x = fmaxf(v1.x, 0.f); v1.y = fmaxf(v1.y, 0.f);
            }
            if (WF32) {
                *(float2*)(C + (size_t)row * ldc + coff + col) = v0;
                *(float2*)(C + (size_t)(row + 8) * ldc + coff + col) = v1;
            }
            if (WH16) {
                *(uint32_t*)(S + (size_t)row * lds_ + scoff + col) = pack_h2(v0.x, v0.y);
                *(uint32_t*)(S + (size_t)(row + 8) * lds_ + scoff + col) = pack_h2(v1.x, v1.y);
            }
        }
    }
}

// 2-stage BN-template mainloop for the fused kernels (low-register form)
#define MAINLOOP_F(AG, LDA, WHG, KK)                                             \
    const int lr = tid >> 2, seg = tid & 3;                                      \
    const int t7 = lane & 7, mi = lane >> 3;                                     \
    const int aRow0 = wr * 32 + t7 + (mi & 1) * 8;                               \
    const int aCol  = (mi >> 1) * 4;                                             \
    const int bRow0 = wc * (BNV / 2) + t7 + (mi >> 1) * 8;                       \
    const int bCol  = (mi & 1) * 4;                                              \
    const int nc = (KK) >> 5;                                                    \
    auto issue = [&](int c, int buf) {                                           \
        const int k0 = c << 5;                                                   \
        const uint32_t sb = sbase + buf * (STGV * 4);                            \
        for (int it = 0; it < 2; it++) {                                         \
            const int r = lr + it * 64;                                          \
            cp16(sb + (r * 20 + seg * 4) * 4,                                    \
                 (AG) + (size_t)(m0 + r) * (LDA) + k0 + seg * 8);                \
        }                                                                        \
        for (int i = tid; i < BNV * 4; i += 256) {                               \
            const int r = i >> 2, sg = i & 3;                                    \
            cp16(sb + (2560 + r * 20 + sg * 4) * 4,                              \
                 (WHG) + (size_t)r * (KK) + k0 + sg * 8);                        \
        }                                                                        \
    };                                                                           \
    issue(0, 0); cp_commit();                                                    \
    for (int c = 0; c < nc; c++) {                                               \
        if (c + 1 < nc) issue(c + 1, (c + 1) & 1);                               \
        cp_commit(); cp_wait1(); __syncthreads();                                \
        const uint32_t sb = sbase + (c & 1) * (STGV * 4);                        \
        for (int s = 0; s < 2; s++) {                                            \
            uint32_t ah[2][4];                                                   \
            for (int i = 0; i < 2; i++) {                                        \
                const uint32_t ai =                                              \
                    (uint32_t)((aRow0 + i * 16) * 20 + s * 8 + aCol) * 4;        \
                ldsm_x4(ah[i], sb + ai);                                         \
            }                                                                    \
            for (int jp = 0; jp < NJV / 2; jp++) {                               \
                const uint32_t bi =                                              \
                    (uint32_t)((bRow0 + jp * 16) * 20 + s * 8 + bCol) * 4;       \
                uint32_t tb[4];                                                  \
                ldsm_x4(tb, sb + 2560 * 4 + bi);                                 \
                mma16816(acc[0][2 * jp],     ah[0], tb);                         \
                mma16816(acc[0][2 * jp + 1], ah[0], tb + 2);                     \
                mma16816(acc[1][2 * jp],     ah[1], tb);                         \
                mma16816(acc[1][2 * jp + 1], ah[1], tb + 2);                     \
            }                                                                    \
        }                                                                        \
        __syncthreads();                                                         \
    }

// ---------------------------------------------------------------------------
// Fused GEMM + residual + LayerNorm (verified epilogue).
// ---------------------------------------------------------------------------
template<int MODE>
__global__ void __launch_bounds__(256)
gemm_ln(const fp16* __restrict__ Ag, int lda,
        const fp16* __restrict__ Whg,
        const float* __restrict__ bias,
        const float* __restrict__ RES,
        const float* __restrict__ gam, const float* __restrict__ bet,
        float* __restrict__ Xout, fp16* __restrict__ Xh,
        int K)
{
    constexpr int BNV = 192, NJV = 12;
    constexpr int STGV = StgSz<192>::v;
    extern __shared__ __align__(16) uint32_t sm32[];
    __shared__ float rsum[128][2], rssq[128][2];
    const uint32_t sbase = smem_u32(sm32);
    const int tid = threadIdx.x;
    const int wid = tid >> 5, lane = tid & 31;
    const int wr = wid >> 1, wc = wid & 1;
    const int m0 = blockIdx.y * 128;

    float acc[2][NJV][4];
#pragma unroll
    for (int i = 0; i < 2; i++)
#pragma unroll
        for (int j = 0; j < NJV; j++)
#pragma unroll
            for (int q = 0; q < 4; q++) acc[i][j][q] = 0.f;

    MAINLOOP_F(Ag, lda, Whg, K)

    const int lg = lane >> 2, lq = lane & 3;
    float sP[4] = {0.f, 0.f, 0.f, 0.f}, ssP[4] = {0.f, 0.f, 0.f, 0.f};
#pragma unroll
    for (int i = 0; i < 2; i++)
#pragma unroll
        for (int h = 0; h < 2; h++) {
            const int row = m0 + wr * 32 + i * 16 + h * 8 + lg;
            const float* rp = RES + (size_t)row * 192;
            const int slot = i * 2 + h;
#pragma unroll
            for (int j = 0; j < NJV; j++) {
                const int col = wc * 96 + j * 8 + 2 * lq;
                float2 r2 = *(const float2*)(rp + col);
                float y0 = acc[i][j][2 * h]     + bias[col]     + r2.x;
                float y1 = acc[i][j][2 * h + 1] + bias[col + 1] + r2.y;
                acc[i][j][2 * h] = y0; acc[i][j][2 * h + 1] = y1;
                sP[slot] += y0 + y1;
                ssP[slot] += y0 * y0 + y1 * y1;
            }
        }
#pragma unroll
    for (int slot = 0; slot < 4; slot++)
#pragma unroll
        for (int d = 1; d < 4; d <<= 1) {
            sP[slot]  += __shfl_xor_sync(0xffffffffu, sP[slot], d);
            ssP[slot] += __shfl_xor_sync(0xffffffffu, ssP[slot], d);
        }
    if (lq == 0) {
#pragma unroll
        for (int i = 0; i < 2; i++)
#pragma unroll
            for (int h = 0; h < 2; h++) {
                const int lrow = wr * 32 + i * 16 + h * 8 + lg;
                rsum[lrow][wc] = sP[i * 2 + h];
                rssq[lrow][wc] = ssP[i * 2 + h];
            }
    }
    __syncthreads();

#pragma unroll
    for (int i = 0; i < 2; i++)
#pragma unroll
        for (int h = 0; h < 2; h++) {
            const int lrow = wr * 32 + i * 16 + h * 8 + lg;
            const int row = m0 + lrow;
            const float mu = (rsum[lrow][0] + rsum[lrow][1]) * (1.f / 192.f);
            const float rs = rsqrtf((rssq[lrow][0] + rssq[lrow][1]) * (1.f / 192.f)
                                    - mu * mu + 1e-5f);
#pragma unroll
            for (int j = 0; j < NJV; j++) {
                const int col = wc * 96 + j * 8 + 2 * lq;
                float v0 = (acc[i][j][2 * h]     - mu) * rs * gam[col]     + bet[col];
                float v1 = (acc[i][j][2 * h + 1] - mu) * rs * gam[col + 1] + bet[col + 1];
                if (MODE == 1) {
                    *(float2*)(Xout + (size_t)row * 192 + col) = make_float2(v0, v1);
                    *(uint32_t*)(Xh + (size_t)row * 192 + col) = pack_h2(v0, v1);
                } else {
                    float p0 = __shfl_xor_sync(0xffffffffu, v0, 4);
                    float p1 = __shfl_xor_sync(0xffffffffu, v1, 4);
                    if ((lg & 1) == 0) {
                        *(uint32_t*)(Xh + (size_t)(row >> 1) * 192 + col) =
                            pack_h2(0.5f * (v0 + p0), 0.5f * (v1 + p1));
                    }
                }
            }
        }
}

// ---------------------------------------------------------------------------
// Fused classifier head (verified) — BN=192, out[k*B+row].
// ---------------------------------------------------------------------------
__global__ void __launch_bounds__(256)
gemm_cls(const fp16* __restrict__ Ag,
         const fp16* __restrict__ Whg,
         const float* __restrict__ bias,
         const float* __restrict__ w2, const float* __restrict__ b2,
         float* __restrict__ out, int Bn)
{
    constexpr int BNV = 192, NJV = 12;
    constexpr int STGV = StgSz<192>::v;
    extern __shared__ __align__(16) uint32_t sm32[];
    __shared__ float lsum[128][2][3];
    const uint32_t sbase = smem_u32(sm32);
    const int tid = threadIdx.x;
    const int wid = tid >> 5, lane = tid & 31;
    const int wr = wid >> 1, wc = wid & 1;
    const int m0 = blockIdx.y * 128;
    const int lda = 192, K = 192;

    float acc[2][NJV][4];
#pragma unroll
    for (int i = 0; i < 2; i++)
#pragma unroll
        for (int j = 0; j < NJV; j++)
#pragma unroll
            for (int q = 0; q < 4; q++) acc[i][j][q] = 0.f;

    MAINLOOP_F(Ag, lda, Whg, K)

    const int lg = lane >> 2, lq = lane & 3;
    float lp[4][3];
#pragma unroll
    for (int s2 = 0; s2 < 4; s2++) { lp[s2][0] = 0.f; lp[s2][1] = 0.f; lp[s2][2] = 0.f; }
#pragma unroll
    for (int i = 0; i < 2; i++)
#pragma unroll
        for (int h = 0; h < 2; h++) {
            const int slot = i * 2 + h;
#pragma unroll
            for (int j = 0; j < NJV; j++) {
                const int col = wc * 96 + j * 8 + 2 * lq;
                float c0 = fmaxf(acc[i][j][2 * h]     + bias[col], 0.f);
                float c1 = fmaxf(acc[i][j][2 * h + 1] + bias[col + 1], 0.f);
#pragma unroll
                for (int k = 0; k < 3; k++)
                    lp[slot][k] += c0 * w2[k * 192 + col] + c1 * w2[k * 192 + col + 1];
            }
        }
#pragma unroll
    for (int slot = 0; slot < 4; slot++)
#pragma unroll
        for (int k = 0; k < 3; k++)
#pragma unroll
            for (int d = 1; d < 4; d <<= 1)
                lp[slot][k] += __shfl_xor_sync(0xffffffffu, lp[slot][k], d);
    if (lq == 0) {
#pragma unroll
        for (int i = 0; i < 2; i++)
#pragma unroll
            for (int h = 0; h < 2; h++) {
                const int lrow = wr * 32 + i * 16 + h * 8 + lg;
#pragma unroll
                for (int k = 0; k < 3; k++) lsum[lrow][wc][k] = lp[i * 2 + h][k];
            }
    }
    __syncthreads();
    if (lq == 0 && wc == 0) {
#pragma unroll
        for (int i = 0; i < 2; i++)
#pragma unroll
            for (int h = 0; h < 2; h++) {
                const int lrow = wr * 32 + i * 16 + h * 8 + lg;
                const int row = m0 + lrow;
#pragma unroll
                for (int k = 0; k < 3; k++) {
                    float l = lsum[lrow][0][k] + lsum[lrow][1][k] + b2[k];
                    out[(size_t)k * Bn + row] = 1.f / (1.f + expf(-l));
                }
            }
    }
}

// ---------------------------------------------------------------------------
// Fused fingerprint head (verified) — BN=128, normalized rows to out+3B.
// ---------------------------------------------------------------------------
__global__ void __launch_bounds__(256)
gemm_fp(const fp16* __restrict__ Ag,
        const fp16* __restrict__ Whg,
        const float* __restrict__ bias,
        float* __restrict__ out, int Bn)
{
    constexpr int BNV = 128, NJV = 8;
    constexpr int STGV = StgSz<128>::v;
    extern __shared__ __align__(16) uint32_t sm32[];
    __shared__ float rssq[128][2];
    const uint32_t sbase = smem_u32(sm32);
    const int tid = threadIdx.x;
    const int wid = tid >> 5, lane = tid & 31;
    const int wr = wid >> 1, wc = wid & 1;
    const int m0 = blockIdx.y * 128;
    const int lda = 192, K = 192;

    float acc[2][NJV][4];
#pragma unroll
    for (int i = 0; i < 2; i++)
#pragma unroll
        for (int j = 0; j < NJV; j++)
#pragma unroll
            for (int q = 0; q < 4; q++) acc[i][j][q] = 0.f;

    MAINLOOP_F(Ag, lda, Whg, K)

    const int lg = lane >> 2, lq = lane & 3;
    float ssP[4] = {0.f, 0.f, 0.f, 0.f};
#pragma unroll
    for (int i = 0; i < 2; i++)
#pragma unroll
        for (int h = 0; h < 2; h++) {
            const int slot = i * 2 + h;
#pragma unroll
            for (int j = 0; j < NJV; j++) {
                const int col = wc * 64 + j * 8 + 2 * lq;
                float v0 = acc[i][j][2 * h]     + bias[col];
                float v1 = acc[i][j][2 * h + 1] + bias[col + 1];
                acc[i][j][2 * h] = v0; acc[i][j][2 * h + 1] = v1;
                ssP[slot] += v0 * v0 + v1 * v1;
            }
        }
#pragma unroll
    for (int slot = 0; slot < 4; slot++)
#pragma unroll
        for (int d = 1; d < 4; d <<= 1)
            ssP[slot] += __shfl_xor_sync(0xffffffffu, ssP[slot], d);
    if (lq == 0) {
#pragma unroll
        for (int i = 0; i < 2; i++)
#pragma unroll
            for (int h = 0; h < 2; h++)
                rssq[wr * 32 + i * 16 + h * 8 + lg][wc] = ssP[i * 2 + h];
    }
    __syncthreads();

#pragma unroll
    for (int i = 0; i < 2; i++)
#pragma unroll
        for (int h = 0; h < 2; h++) {
            const int lrow = wr * 32 + i * 16 + h * 8 + lg;
            const int row = m0 + lrow;
            const float nrm = sqrtf(rssq[lrow][0] + rssq[lrow][1]);
            const float sc = 1.f / fmaxf(nrm, 1e-12f);
            float* op = out + 3L * Bn + (size_t)row * 128;
#pragma unroll
            for (int j = 0; j < NJV; j++) {
                const int col = wc * 64 + j * 8 + 2 * lq;
                *(float2*)(op + col) =
                    make_float2(acc[i][j][2 * h] * sc, acc[i][j][2 * h + 1] * sc);
            }
        }
}

// ---------------- attention ----------------
__global__ void attn_kernel(const fp16* __restrict__ qkv, fp16* __restrict__ ch, int B)
{
    const int w = (blockIdx.x * blockDim.x + threadIdx.x) >> 5;
    const int lane = threadIdx.x & 31;
    if (w >= B) return;
    const fp16* r0 = qkv + (size_t)(2 * w) * 576;
    const fp16* r1 = r0 + 576;
    const size_t o0r = (size_t)(2 * w) * 192, o1r = o0r + 192;
#pragma unroll
    for (int h = 0; h < 3; h++) {
        const int o = h * 64 + 2 * lane;
        float2 q0 = __half22float2(*(const __half2*)(r0 + o));
        float2 q1 = __half22float2(*(const __half2*)(r1 + o));
        float2 k0 = __half22float2(*(const __half2*)(r0 + 192 + o));
        float2 k1 = __half22float2(*(const __half2*)(r1 + 192 + o));
        float2 v0 = __half22float2(*(const __half2*)(r0 + 384 + o));
        float2 v1 = __half22float2(*(const __half2*)(r1 + 384 + o));
        float s00 = q0.x * k0.x + q0.y * k0.y;
        float s01 = q0.x * k1.x + q0.y * k1.y;
        float s10 = q1.x * k0.x + q1.y * k0.y;
        float s11 = q1.x * k1.x + q1.y * k1.y;
#pragma unroll
        for (int d = 16; d; d >>= 1) {
            s00 += __shfl_xor_sync(0xffffffffu, s00, d);
            s01 += __shfl_xor_sync(0xffffffffu, s01, d);
            s10 += __shfl_xor_sync(0xffffffffu, s10, d);
            s11 += __shfl_xor_sync(0xffffffffu, s11, d);
        }
        s00 *= 0.125f; s01 *= 0.125f; s10 *= 0.125f; s11 *= 0.125f;
        float m0 = fmaxf(s00, s01);
        float e00 = expf(s00 - m0), e01 = expf(s01 - m0);
        float i0 = 1.f / (e00 + e01);
        float m1 = fmaxf(s10, s11);
        float e10 = expf(s10 - m1), e11 = expf(s11 - m1);
        float i1 = 1.f / (e10 + e11);
        float a00 = e00 * i0, a01 = e01 * i0, a10 = e10 * i1, a11 = e11 * i1;
        *(uint32_t*)(ch + o0r + o) = pack_h2(a00 * v0.x + a01 * v1.x, a00 * v0.y + a01 * v1.y);
        *(uint32_t*)(ch + o1r + o) = pack_h2(a10 * v0.x + a11 * v1.x, a10 * v0.y + a11 * v1.y);
    }
}

// ---------------- host ----------------
static inline void dsym(void** p, const void* sym) { cudaGetSymbolAddress(p, sym); }

extern "C" void kernel_launch(void* const* d_in, const int* in_sizes, int n_in,
                              void* d_out, int out_size)
{
    const float* perc   = (const float*)d_in[0];
    const float* tech   = (const float*)d_in[1];
    const float* Wp     = (const float*)d_in[2];
    const float* bp     = (const float*)d_in[3];
    const float* Wt     = (const float*)d_in[4];
    const float* bt     = (const float*)d_in[5];
    const float* in_w   = (const float*)d_in[6];
    const float* in_b   = (const float*)d_in[7];
    const float* out_w  = (const float*)d_in[8];
    const float* out_b  = (const float*)d_in[9];
    const float* ffn_w1 = (const float*)d_in[10];
    const float* ffn_b1 = (const float*)d_in[11];
    const float* ffn_w2 = (const float*)d_in[12];
    const float* ffn_b2 = (const float*)d_in[13];
    const float* ln1_g  = (const float*)d_in[14];
    const float* ln1_b  = (const float*)d_in[15];
    const float* ln2_g  = (const float*)d_in[16];
    const float* ln2_b  = (const float*)d_in[17];
    const float* cls_w1 = (const float*)d_in[18];
    const float* cls_b1 = (const float*)d_in[19];
    const float* cls_w2 = (const float*)d_in[20];
    const float* cls_b2 = (const float*)d_in[21];
    const float* fp_w   = (const float*)d_in[22];
    const float* fp_b   = (const float*)d_in[23];

    int B = in_sizes[0] / DM;
    if (B > MAXB) B = MAXB;
    const int T = 2 * B;

    float *seq, *x;
    dsym((void**)&seq, g_seq); dsym((void**)&x, g_x);

    fp16 *pa, *ta, *seqh, *qkvh, *ctxh, *xh, *hh, *zh, *whi;
    dsym((void**)&pa, g_pa); dsym((void**)&ta, g_ta);
    dsym((void**)&seqh, g_seqh); dsym((void**)&qkvh, g_qkvh);
    dsym((void**)&ctxh, g_ctxh);
    dsym((void**)&xh, g_xh); dsym((void**)&hh, g_hh); dsym((void**)&zh, g_zh);
    dsym((void**)&whi, g_whi);

    cudaFuncSetAttribute(tc_gemm<96, false, true,  true >, cudaFuncAttributeMaxDynamicSharedMemorySize, GEMM_SMEM96);
    cudaFuncSetAttribute(tc_gemm<96, false, false, true >, cudaFuncAttributeMaxDynamicSharedMemorySize, GEMM_SMEM96);
    cudaFuncSetAttribute(tc_gemm<96, true,  false, true >, cudaFuncAttributeMaxDynamicSharedMemorySize, GEMM_SMEM96);
    cudaFuncSetAttribute(gemm_ln<1>, cudaFuncAttributeMaxDynamicSharedMemorySize, LN_SMEM);
    cudaFuncSetAttribute(gemm_ln<2>, cudaFuncAttributeMaxDynamicSharedMemorySize, LN_SMEM);
    cudaFuncSetAttribute(gemm_cls, cudaFuncAttributeMaxDynamicSharedMemorySize, LN_SMEM);
    cudaFuncSetAttribute(gemm_fp,  cudaFuncAttributeMaxDynamicSharedMemorySize, FP_SMEM);

    float* out = (float*)d_out;

    cvt_weights<<<(OW_TOT / 4 + 255) / 256, 256>>>(
        Wp, Wt, in_w, out_w, ffn_w1, ffn_w2, cls_w1, fp_w, whi);
    cvt_k<<<(int)(((long)B * 192 / 4 + 255) / 256), 256>>>(perc, pa, (long)B * 192);
    cvt_k<<<(int)(((long)B * 192 / 4 + 255) / 256), 256>>>(tech, ta, (long)B * 192);

    // projections -> seq fp32 + fp16 (seq stored [B,384]; token view [2B,192])
    tc_gemm<96, false, true, true><<<dim3(2, B / 128), 256, GEMM_SMEM96>>>(
        pa, 192, whi + OW_P, bp, seq, 384, 0, seqh, 384, 0, 192);
    tc_gemm<96, false, true, true><<<dim3(2, B / 128), 256, GEMM_SMEM96>>>(
        ta, 192, whi + OW_T, bt, seq, 384, 192, seqh, 384, 192, 192);
    // qkv fp16: token view lda 192
    tc_gemm<96, false, false, true><<<dim3(6, T / 128), 256, GEMM_SMEM96>>>(
        seqh, 192, whi + OW_IN, in_b, nullptr, 0, 0, qkvh, 576, 0, 192);
    attn_kernel<<<(B + 7) / 8, 256>>>(qkvh, ctxh, B);
    // out-proj fused +seq residual + LN1
    gemm_ln<1><<<dim3(1, T / 128), 256, LN_SMEM>>>(
        ctxh, 192, whi + OW_OUT, out_b, seq, ln1_g, ln1_b, x, xh, 192);
    // ffn1
    tc_gemm<96, true, false, true><<<dim3(4, T / 128), 256, GEMM_SMEM96>>>(
        xh, 192, whi + OW_F1, ffn_b1, nullptr, 0, 0, hh, 384, 0, 192);
    // ffn2 fused +x residual + LN2 + token mean
    gemm_ln<2><<<dim3(1, T / 128), 256, LN_SMEM>>>(
        hh, 384, whi + OW_F2, ffn_b2, x, ln2_g, ln2_b, nullptr, zh, 384);
    // fused heads -> out
    gemm_cls<<<dim3(1, B / 128), 256, LN_SMEM>>>(
        zh, whi + OW_CLS, cls_b1, cls_w2, cls_b2, out, B);
    gemm_fp<<<dim3(1, B / 128), 256, FP_SMEM>>>(
        zh, whi + OW_FP, fp_b, out, B);
}